// round 6
// baseline (speedup 1.0000x reference)
#include <cuda_runtime.h>
#include <math.h>

// ---------------------------------------------------------------------------
// GaussianRasterizer — tile x N-segment decomposition, single kernel.
// Grid (tilesX, tilesY, NSEG): each 128-thread CTA rasterizes one 16x8 tile
// against one N/NSEG segment. Partials go to __device__ scratch; the last
// CTA to finish a tile (ticket) sums the NSEG partials in fixed z order
// (bit-deterministic) and writes d_out, then resets the ticket for the
// next graph replay.
// ---------------------------------------------------------------------------

#define TILE_W 16
#define TILE_H 8
#define NT 128
#define CPT 4
#define CHUNK (NT * CPT)       // 512 candidates per chunk
#define NSEG 4
#define MAXTILES 4096
#define TPIX (NT * 3)          // floats per tile partial (384)

__device__ float g_part[MAXTILES][NSEG][TPIX];
__device__ int   g_ticket[MAXTILES];   // static-zero initialized

__device__ __forceinline__ float scalar_as_float(const int* p) {
    int v = *p;
    if (v >= 0 && v <= 1000000) return (float)v;
    return __int_as_float(v);
}

__device__ __forceinline__ float ex2(float q) {
    float r;
    asm("ex2.approx.ftz.f32 %0, %1;" : "=f"(r) : "f"(q));
    return r;
}

__global__ __launch_bounds__(NT)
void gr_raster(const float* __restrict__ opacity,
               const float* __restrict__ means,
               const float* __restrict__ stds,
               const float* __restrict__ rhos,
               const float* __restrict__ colors,
               const int*   __restrict__ scale_p,
               const int*   __restrict__ ratio_p,
               float* __restrict__ out, int N, int W, int H) {
    // Survivor SoA: s0 = {mx, my, qa, qb2}, s1 = {qc, cr, cg, cb}
    // qa/qb2/qc have (-0.5 * log2 e) folded in: weight = 2^q.
    __shared__ float4 s0[CHUNK];
    __shared__ float4 s1[CHUNK];
    __shared__ int    swc[NT / 32];
    __shared__ int    s_ticket;

    const int tid  = threadIdx.x;
    const int lane = tid & 31;
    const int wid  = tid >> 5;
    const int z    = blockIdx.z;
    const int tile = blockIdx.y * gridDim.x + blockIdx.x;

    const int px = blockIdx.x * TILE_W + (tid & (TILE_W - 1));
    const int py = blockIdx.y * TILE_H + (tid / TILE_W);
    const float x = (float)px + 0.5f;
    const float y = (float)py + 0.5f;

    const float tcx = (float)(blockIdx.x * TILE_W) + 0.5f + (TILE_W - 1) * 0.5f;
    const float tcy = (float)(blockIdx.y * TILE_H) + 0.5f + (TILE_H - 1) * 0.5f;
    const float thx = (TILE_W - 1) * 0.5f;
    const float thy = (TILE_H - 1) * 0.5f;

    const float s    = scalar_as_float(scale_p);
    const float r    = scalar_as_float(ratio_p);
    const float rs   = r * s;
    const float HL2E = -0.5f * 1.44269504088896340736f;  // -0.5*log2(e)
    const float cth  = HL2E * r * r;     // pass when folded q >= cth

    const float2* __restrict__ mean2 = (const float2*)means;
    const float2* __restrict__ std2  = (const float2*)stds;

    const int segN = (N + NSEG - 1) / NSEG;
    const int beg  = z * segN;
    const int end  = min(N, beg + segN);

    float ar0 = 0.f, ag0 = 0.f, ab0 = 0.f;
    float ar1 = 0.f, ag1 = 0.f, ab1 = 0.f;

    for (int base = beg; base < end; base += CHUNK) {
        // ---- Cull: CPT contiguous candidates per thread.
        const int ib = base + tid * CPT;
        float2 mk[CPT], sk[CPT];
        unsigned hm = 0;
        int cnt = 0;
        #pragma unroll
        for (int k = 0; k < CPT; k++) {
            int i = ib + k;
            if (i < end) {
                mk[k] = mean2[i];
                sk[k] = std2[i];
                bool hit = (fabsf(mk[k].x - tcx) <= fmaf(rs, sk[k].x, thx)) &
                           (fabsf(mk[k].y - tcy) <= fmaf(rs, sk[k].y, thy));
                if (hit) { hm |= (1u << k); cnt++; }
            }
        }

        // ---- Deterministic CTA-level scan.
        int incl = cnt;
        #pragma unroll
        for (int d = 1; d < 32; d <<= 1) {
            int v = __shfl_up_sync(0xffffffffu, incl, d);
            if (lane >= d) incl += v;
        }
        if (lane == 31) swc[wid] = incl;
        __syncthreads();                       // swc ready; prev eval done

        int off = 0, total = 0;
        #pragma unroll
        for (int w = 0; w < NT / 32; w++) {
            int c = swc[w];
            if (w < wid) off += c;
            total += c;
        }
        int slot = off + (incl - cnt);

        // ---- Compaction: inverse covariance only for survivors.
        #pragma unroll
        for (int k = 0; k < CPT; k++) {
            if ((hm >> k) & 1u) {
                int i = ib + k;
                float rho = rhos[i];
                float o   = opacity[i];
                float c0  = colors[3 * i + 0];
                float c1  = colors[3 * i + 1];
                float c2  = colors[3 * i + 2];
                float sx  = sk[k].x * s;
                float sy  = sk[k].y * s;
                float om  = 1.0f - rho * rho;
                float qa  = __fdividef(HL2E,               sx * sx * om);
                float qc  = __fdividef(HL2E,               sy * sy * om);
                float qb2 = __fdividef(-2.0f * HL2E * rho, sx * sy * om);
                s0[slot] = make_float4(mk[k].x, mk[k].y, qa, qb2);
                s1[slot] = make_float4(qc, o * c0, o * c1, o * c2);
                slot++;
            }
        }
        __syncthreads();                       // survivor list ready

        // ---- Eval: branch-free, 2-way unrolled, dual accumulators.
        int j = 0;
        for (; j + 1 < total; j += 2) {
            float4 a0 = s0[j],     b0 = s1[j];
            float4 a1 = s0[j + 1], b1 = s1[j + 1];

            float dx0 = x - a0.x, dy0 = y - a0.y;
            float q0  = a0.z * dx0 * dx0;
            q0 = fmaf(a0.w * dx0, dy0, q0);
            q0 = fmaf(b0.x * dy0, dy0, q0);

            float dx1 = x - a1.x, dy1 = y - a1.y;
            float q1  = a1.z * dx1 * dx1;
            q1 = fmaf(a1.w * dx1, dy1, q1);
            q1 = fmaf(b1.x * dy1, dy1, q1);

            float w0 = ex2(q0);
            float w1 = ex2(q1);
            w0 = (q0 >= cth) ? w0 : 0.0f;
            w1 = (q1 >= cth) ? w1 : 0.0f;

            ar0 = fmaf(w0, b0.y, ar0);
            ag0 = fmaf(w0, b0.z, ag0);
            ab0 = fmaf(w0, b0.w, ab0);
            ar1 = fmaf(w1, b1.y, ar1);
            ag1 = fmaf(w1, b1.z, ag1);
            ab1 = fmaf(w1, b1.w, ab1);
        }
        if (j < total) {
            float4 a0 = s0[j], b0 = s1[j];
            float dx0 = x - a0.x, dy0 = y - a0.y;
            float q0  = a0.z * dx0 * dx0;
            q0 = fmaf(a0.w * dx0, dy0, q0);
            q0 = fmaf(b0.x * dy0, dy0, q0);
            float w0 = ex2(q0);
            w0 = (q0 >= cth) ? w0 : 0.0f;
            ar0 = fmaf(w0, b0.y, ar0);
            ag0 = fmaf(w0, b0.z, ag0);
            ab0 = fmaf(w0, b0.w, ab0);
        }
    }

    const float pr = ar0 + ar1;
    const float pg = ag0 + ag1;
    const float pb = ab0 + ab1;

    // ---- Publish this segment's partial, take a ticket.
    float* mypart = g_part[tile][z];
    mypart[tid * 3 + 0] = pr;
    mypart[tid * 3 + 1] = pg;
    mypart[tid * 3 + 2] = pb;
    __threadfence();
    __syncthreads();
    if (tid == 0) s_ticket = atomicAdd(&g_ticket[tile], 1);
    __syncthreads();

    // ---- Last CTA for this tile: fixed-z-order reduction, write out.
    if (s_ticket == NSEG - 1) {
        __threadfence();   // acquire: other segments' partials visible
        float sr = 0.f, sg = 0.f, sb = 0.f;
        #pragma unroll
        for (int zz = 0; zz < NSEG; zz++) {
            if (zz == z) {
                sr += pr; sg += pg; sb += pb;
            } else {
                const float* p = g_part[tile][zz];
                sr += p[tid * 3 + 0];
                sg += p[tid * 3 + 1];
                sb += p[tid * 3 + 2];
            }
        }
        if (px < W && py < H) {
            int o = (py * W + px) * 3;
            out[o + 0] = sr;
            out[o + 1] = sg;
            out[o + 2] = sb;
        }
        __syncthreads();
        if (tid == 0) g_ticket[tile] = 0;   // reset for next graph replay
    }
}

extern "C" void kernel_launch(void* const* d_in, const int* in_sizes, int n_in,
                              void* d_out, int out_size) {
    const float* opacity = (const float*)d_in[0];
    const float* means   = (const float*)d_in[1];
    const float* stds    = (const float*)d_in[2];
    const float* rhos    = (const float*)d_in[3];
    const float* colors  = (const float*)d_in[4];
    const int*   scale_p = (const int*)d_in[7];
    const int*   ratio_p = (const int*)d_in[8];

    int N = in_sizes[0];

    int hw = out_size / 3;
    int W = (int)lrint(sqrt((double)hw));
    while (W > 1 && (hw % W) != 0) W--;
    int H = hw / W;

    float* out = (float*)d_out;

    dim3 grid((W + TILE_W - 1) / TILE_W, (H + TILE_H - 1) / TILE_H, NSEG);
    gr_raster<<<grid, NT>>>(opacity, means, stds, rhos, colors,
                            scale_p, ratio_p, out, N, W, H);
}

// round 7
// speedup vs baseline: 1.0403x; 1.0403x over previous
#include <cuda_runtime.h>
#include <math.h>

// ---------------------------------------------------------------------------
// GaussianRasterizer — one CTA per 16x8 tile, 512 threads = 4 eval-groups.
// All 512 threads cooperatively cull/compact the full Gaussian list (chunks
// of 1024); each 128-thread group then evaluates the survivor subset
// j = g (mod 4) for its pixel. Partials combine deterministically in smem
// (fixed group order). Single kernel, no atomics, no fences.
// ---------------------------------------------------------------------------

#define TILE_W 16
#define TILE_H 8
#define NT 512
#define NG 4
#define GSZ 128                  // threads (=pixels) per group
#define CPT 2
#define CHUNK (NT * CPT)         // 1024 candidates per chunk
#define NW (NT / 32)             // 16 warps

__device__ __forceinline__ float scalar_as_float(const int* p) {
    int v = *p;
    if (v >= 0 && v <= 1000000) return (float)v;
    return __int_as_float(v);
}

__device__ __forceinline__ float ex2(float q) {
    float r;
    asm("ex2.approx.ftz.f32 %0, %1;" : "=f"(r) : "f"(q));
    return r;
}

__global__ __launch_bounds__(NT, 3)
void gr_raster(const float* __restrict__ opacity,
               const float* __restrict__ means,
               const float* __restrict__ stds,
               const float* __restrict__ rhos,
               const float* __restrict__ colors,
               const int*   __restrict__ scale_p,
               const int*   __restrict__ ratio_p,
               float* __restrict__ out, int N, int W, int H) {
    // Survivor SoA: s0 = {mx, my, qa, qb2}, s1 = {qc, cr, cg, cb}
    // qa/qb2/qc carry (-0.5 * log2 e): weight = 2^q.
    __shared__ float4 s0[CHUNK];
    __shared__ float4 s1[CHUNK];
    __shared__ int    swc[NW];
    __shared__ float  sacc[NG - 1][GSZ][3];

    const int tid  = threadIdx.x;
    const int lane = tid & 31;
    const int wid  = tid >> 5;
    const int g    = tid >> 7;          // eval group 0..3
    const int htid = tid & (GSZ - 1);   // pixel index within tile

    const int px = blockIdx.x * TILE_W + (htid & (TILE_W - 1));
    const int py = blockIdx.y * TILE_H + (htid / TILE_W);
    const float x = (float)px + 0.5f;
    const float y = (float)py + 0.5f;

    const float tcx = (float)(blockIdx.x * TILE_W) + 0.5f + (TILE_W - 1) * 0.5f;
    const float tcy = (float)(blockIdx.y * TILE_H) + 0.5f + (TILE_H - 1) * 0.5f;
    const float thx = (TILE_W - 1) * 0.5f;
    const float thy = (TILE_H - 1) * 0.5f;

    const float s    = scalar_as_float(scale_p);
    const float r    = scalar_as_float(ratio_p);
    const float rs   = r * s;
    const float HL2E = -0.5f * 1.44269504088896340736f;  // -0.5*log2(e)
    const float cth  = HL2E * r * r;     // pass when folded q >= cth

    const float2* __restrict__ mean2 = (const float2*)means;
    const float2* __restrict__ std2  = (const float2*)stds;

    float ar0 = 0.f, ag0 = 0.f, ab0 = 0.f;
    float ar1 = 0.f, ag1 = 0.f, ab1 = 0.f;

    for (int base = 0; base < N; base += CHUNK) {
        // ---- Cull: CPT contiguous candidates per thread (all 512 threads).
        const int ib = base + tid * CPT;
        float2 mk[CPT], sk[CPT];
        unsigned hm = 0;
        int cnt = 0;
        #pragma unroll
        for (int k = 0; k < CPT; k++) {
            int i = ib + k;
            if (i < N) {
                mk[k] = mean2[i];
                sk[k] = std2[i];
                bool hit = (fabsf(mk[k].x - tcx) <= fmaf(rs, sk[k].x, thx)) &
                           (fabsf(mk[k].y - tcy) <= fmaf(rs, sk[k].y, thy));
                if (hit) { hm |= (1u << k); cnt++; }
            }
        }

        // ---- Deterministic block scan (warp scan + 16-entry combine).
        int incl = cnt;
        #pragma unroll
        for (int d = 1; d < 32; d <<= 1) {
            int v = __shfl_up_sync(0xffffffffu, incl, d);
            if (lane >= d) incl += v;
        }
        if (lane == 31) swc[wid] = incl;
        __syncthreads();                       // swc ready; prev eval done

        int off = 0, total = 0;
        #pragma unroll
        for (int w = 0; w < NW; w++) {
            int c = swc[w];
            if (w < wid) off += c;
            total += c;
        }
        int slot = off + (incl - cnt);

        // ---- Compaction: inverse covariance only for survivors.
        #pragma unroll
        for (int k = 0; k < CPT; k++) {
            if ((hm >> k) & 1u) {
                int i = ib + k;
                float rho = rhos[i];
                float o   = opacity[i];
                float c0  = colors[3 * i + 0];
                float c1  = colors[3 * i + 1];
                float c2  = colors[3 * i + 2];
                float sx  = sk[k].x * s;
                float sy  = sk[k].y * s;
                float om  = 1.0f - rho * rho;
                float qa  = __fdividef(HL2E,               sx * sx * om);
                float qc  = __fdividef(HL2E,               sy * sy * om);
                float qb2 = __fdividef(-2.0f * HL2E * rho, sx * sy * om);
                s0[slot] = make_float4(mk[k].x, mk[k].y, qa, qb2);
                s1[slot] = make_float4(qc, o * c0, o * c1, o * c2);
                slot++;
            }
        }
        __syncthreads();                       // survivor list ready

        // ---- Eval: group g takes survivors j = g (mod NG).
        // Dual independent streams for ILP; branch-free weights.
        int j = g;
        for (; j + NG < total; j += 2 * NG) {
            float4 a0 = s0[j],      b0 = s1[j];
            float4 a1 = s0[j + NG], b1 = s1[j + NG];

            float dx0 = x - a0.x, dy0 = y - a0.y;
            float q0  = a0.z * dx0 * dx0;
            q0 = fmaf(a0.w * dx0, dy0, q0);
            q0 = fmaf(b0.x * dy0, dy0, q0);

            float dx1 = x - a1.x, dy1 = y - a1.y;
            float q1  = a1.z * dx1 * dx1;
            q1 = fmaf(a1.w * dx1, dy1, q1);
            q1 = fmaf(b1.x * dy1, dy1, q1);

            float w0 = ex2(q0);
            float w1 = ex2(q1);
            w0 = (q0 >= cth) ? w0 : 0.0f;
            w1 = (q1 >= cth) ? w1 : 0.0f;

            ar0 = fmaf(w0, b0.y, ar0);
            ag0 = fmaf(w0, b0.z, ag0);
            ab0 = fmaf(w0, b0.w, ab0);
            ar1 = fmaf(w1, b1.y, ar1);
            ag1 = fmaf(w1, b1.z, ag1);
            ab1 = fmaf(w1, b1.w, ab1);
        }
        if (j < total) {
            float4 a0 = s0[j], b0 = s1[j];
            float dx0 = x - a0.x, dy0 = y - a0.y;
            float q0  = a0.z * dx0 * dx0;
            q0 = fmaf(a0.w * dx0, dy0, q0);
            q0 = fmaf(b0.x * dy0, dy0, q0);
            float w0 = ex2(q0);
            w0 = (q0 >= cth) ? w0 : 0.0f;
            ar0 = fmaf(w0, b0.y, ar0);
            ag0 = fmaf(w0, b0.z, ag0);
            ab0 = fmaf(w0, b0.w, ab0);
        }
    }

    // ---- Deterministic combine: groups 1..3 publish, group 0 sums in order.
    const float pr = ar0 + ar1;
    const float pg = ag0 + ag1;
    const float pb = ab0 + ab1;

    if (g) {
        sacc[g - 1][htid][0] = pr;
        sacc[g - 1][htid][1] = pg;
        sacc[g - 1][htid][2] = pb;
    }
    __syncthreads();
    if (g == 0 && px < W && py < H) {
        float sr = pr, sg = pg, sb = pb;
        #pragma unroll
        for (int q = 0; q < NG - 1; q++) {
            sr += sacc[q][htid][0];
            sg += sacc[q][htid][1];
            sb += sacc[q][htid][2];
        }
        int o = (py * W + px) * 3;
        out[o + 0] = sr;
        out[o + 1] = sg;
        out[o + 2] = sb;
    }
}

extern "C" void kernel_launch(void* const* d_in, const int* in_sizes, int n_in,
                              void* d_out, int out_size) {
    const float* opacity = (const float*)d_in[0];
    const float* means   = (const float*)d_in[1];
    const float* stds    = (const float*)d_in[2];
    const float* rhos    = (const float*)d_in[3];
    const float* colors  = (const float*)d_in[4];
    const int*   scale_p = (const int*)d_in[7];
    const int*   ratio_p = (const int*)d_in[8];

    int N = in_sizes[0];

    int hw = out_size / 3;
    int W = (int)lrint(sqrt((double)hw));
    while (W > 1 && (hw % W) != 0) W--;
    int H = hw / W;

    float* out = (float*)d_out;

    dim3 grid((W + TILE_W - 1) / TILE_W, (H + TILE_H - 1) / TILE_H);
    gr_raster<<<grid, NT>>>(opacity, means, stds, rhos, colors,
                            scale_p, ratio_p, out, N, W, H);
}